// round 1
// baseline (speedup 1.0000x reference)
#include <cuda_runtime.h>
#include <math.h>

#define Bq   32
#define Hc   384
#define Tn   1024
#define MAXL 4096
#define KDIM (Hc * 3)   // 1152

// ---------------- scratch (static device arrays; no allocation) ----------------
__device__ float g_buf1[(size_t)Bq * Hc * Tn];   // conv1 out -> h1 (in-place LN)
__device__ float g_buf2[(size_t)Bq * Hc * Tn];   // conv2 out
__device__ float g_mean[Bq * Tn];
__device__ float g_rstd[Bq * Tn];
__device__ int   g_dur[Bq * Tn];
__device__ int   g_cum[Bq * Tn];

// ---------------- conv-as-GEMM: Y[b,ho,t] = sum_{hi,k} W[ho,hi,k]*X[b,hi,t+k-1] + bias[ho]
// M=384 (ho), N=B*T (t fastest, tiles never straddle batches), K=1152 ((hi,k), k fastest)
// 128x128x8 tile, 256 threads, 8x8 per thread, double-buffered smem.
__global__ __launch_bounds__(256, 2)
void conv_gemm(const float* __restrict__ X, const float* __restrict__ W,
               const float* __restrict__ bias, float* __restrict__ Y)
{
    const int tid = threadIdx.x;
    const int b   = blockIdx.x >> 3;
    const int t0  = (blockIdx.x & 7) << 7;   // 128-wide t tile
    const int m0  = blockIdx.y << 7;         // 128-wide ho tile

    __shared__ float As[2][8][128];
    __shared__ float Bs[2][8][128];

    float acc[8][8];
#pragma unroll
    for (int i = 0; i < 8; i++)
#pragma unroll
        for (int j = 0; j < 8; j++) acc[i][j] = 0.f;

    const int tx = tid & 15;
    const int ty = tid >> 4;

    const float* Xb = X + (size_t)b * Hc * Tn;

    // initial tile (ks = 0)
#pragma unroll
    for (int e = 0; e < 4; e++) {
        int idx = tid + 256 * e;
        // A: row = idx>>3, kk = idx&7
        int arow = idx >> 3, akk = idx & 7;
        As[0][akk][arow] = W[(size_t)(m0 + arow) * KDIM + akk];
        // B: kk = idx>>7, col = idx&127
        int bkk = idx >> 7, bcol = idx & 127;
        int kidx = bkk;
        int hi = kidx / 3, kr = kidx - hi * 3;
        int t = t0 + bcol + kr - 1;
        Bs[0][bkk][bcol] = ((unsigned)t < (unsigned)Tn) ? Xb[hi * Tn + t] : 0.f;
    }
    __syncthreads();

    int buf = 0;
    for (int ks = 8; ks < KDIM; ks += 8) {
        float ra[4], rb[4];
#pragma unroll
        for (int e = 0; e < 4; e++) {
            int idx = tid + 256 * e;
            int arow = idx >> 3, akk = idx & 7;
            ra[e] = W[(size_t)(m0 + arow) * KDIM + ks + akk];
            int bkk = idx >> 7, bcol = idx & 127;
            int kidx = ks + bkk;
            int hi = kidx / 3, kr = kidx - hi * 3;
            int t = t0 + bcol + kr - 1;
            rb[e] = ((unsigned)t < (unsigned)Tn) ? Xb[hi * Tn + t] : 0.f;
        }
#pragma unroll
        for (int kk = 0; kk < 8; kk++) {
            float4 a0 = *(const float4*)&As[buf][kk][ty * 8];
            float4 a1 = *(const float4*)&As[buf][kk][ty * 8 + 4];
            float4 b0 = *(const float4*)&Bs[buf][kk][tx * 8];
            float4 b1 = *(const float4*)&Bs[buf][kk][tx * 8 + 4];
            float av[8] = {a0.x, a0.y, a0.z, a0.w, a1.x, a1.y, a1.z, a1.w};
            float bv[8] = {b0.x, b0.y, b0.z, b0.w, b1.x, b1.y, b1.z, b1.w};
#pragma unroll
            for (int i = 0; i < 8; i++)
#pragma unroll
                for (int j = 0; j < 8; j++) acc[i][j] = fmaf(av[i], bv[j], acc[i][j]);
        }
#pragma unroll
        for (int e = 0; e < 4; e++) {
            int idx = tid + 256 * e;
            As[buf ^ 1][idx & 7][idx >> 3] = ra[e];
            Bs[buf ^ 1][idx >> 7][idx & 127] = rb[e];
        }
        __syncthreads();
        buf ^= 1;
    }
    // last tile
#pragma unroll
    for (int kk = 0; kk < 8; kk++) {
        float4 a0 = *(const float4*)&As[buf][kk][ty * 8];
        float4 a1 = *(const float4*)&As[buf][kk][ty * 8 + 4];
        float4 b0 = *(const float4*)&Bs[buf][kk][tx * 8];
        float4 b1 = *(const float4*)&Bs[buf][kk][tx * 8 + 4];
        float av[8] = {a0.x, a0.y, a0.z, a0.w, a1.x, a1.y, a1.z, a1.w};
        float bv[8] = {b0.x, b0.y, b0.z, b0.w, b1.x, b1.y, b1.z, b1.w};
#pragma unroll
        for (int i = 0; i < 8; i++)
#pragma unroll
            for (int j = 0; j < 8; j++) acc[i][j] = fmaf(av[i], bv[j], acc[i][j]);
    }

    // epilogue: + bias, store
#pragma unroll
    for (int i = 0; i < 8; i++) {
        int ho = m0 + ty * 8 + i;
        float bi = bias[ho];
        float* yp = Y + ((size_t)b * Hc + ho) * Tn + t0 + tx * 8;
        float4 v0 = make_float4(acc[i][0] + bi, acc[i][1] + bi, acc[i][2] + bi, acc[i][3] + bi);
        float4 v1 = make_float4(acc[i][4] + bi, acc[i][5] + bi, acc[i][6] + bi, acc[i][7] + bi);
        *(float4*)yp = v0;
        *(float4*)(yp + 4) = v1;
    }
}

// ---------------- LN stats over channel dim: one thread per (b,t) ----------------
__global__ void ln_stats(const float* __restrict__ Y)
{
    int b = blockIdx.y;
    int t = blockIdx.x * 256 + threadIdx.x;
    const float* p = Y + (size_t)b * Hc * Tn + t;
    float s = 0.f, s2 = 0.f;
#pragma unroll 8
    for (int h = 0; h < Hc; h++) {
        float v = __ldg(p + (size_t)h * Tn);
        s += v; s2 += v * v;
    }
    float m = s * (1.f / Hc);
    float var = s2 * (1.f / Hc) - m * m;
    g_mean[b * Tn + t] = m;
    g_rstd[b * Tn + t] = rsqrtf(var + 1e-5f);
}

// ---------------- LN apply + relu (elementwise, in-place) ----------------
__global__ void ln_apply_relu(float* __restrict__ Y,
                              const float* __restrict__ g, const float* __restrict__ be)
{
    int i = blockIdx.x * 256 + threadIdx.x;
    int t = i & (Tn - 1);
    int bh = i >> 10;
    int h = bh % Hc;
    int b = bh / Hc;
    float v = (Y[i] - g_mean[b * Tn + t]) * g_rstd[b * Tn + t] * __ldg(g + h) + __ldg(be + h);
    Y[i] = fmaxf(v, 0.f);
}

// ---------------- LN2 + relu + dot(Wl) + duration, fused (no h2 materialization) ----
__global__ void ln_dot_dur(const float* __restrict__ Y2,
                           const float* __restrict__ g, const float* __restrict__ be,
                           const float* __restrict__ Wl, const float* __restrict__ bl,
                           float* __restrict__ durF)
{
    int b = blockIdx.y;
    int t = blockIdx.x * 256 + threadIdx.x;
    const float* p = Y2 + (size_t)b * Hc * Tn + t;
    float m = g_mean[b * Tn + t];
    float r = g_rstd[b * Tn + t];
    float acc = 0.f;
#pragma unroll 8
    for (int h = 0; h < Hc; h++) {
        float v = (__ldg(p + (size_t)h * Tn) - m) * r * __ldg(g + h) + __ldg(be + h);
        acc += fmaxf(v, 0.f) * __ldg(Wl + h);
    }
    float z = fmaxf(acc + __ldg(bl), 0.f);
    int d = (int)floorf(expf(z));
    g_dur[b * Tn + t] = d;
    durF[b * Tn + t] = (float)d;
}

// ---------------- per-batch inclusive cumsum (T=1024, Hillis-Steele) ----------------
__global__ void cumsum_k()
{
    __shared__ int s[Tn];
    int b = blockIdx.x, t = threadIdx.x;
    s[t] = g_dur[b * Tn + t];
    __syncthreads();
#pragma unroll
    for (int off = 1; off < Tn; off <<= 1) {
        int v = (t >= off) ? s[t - off] : 0;
        __syncthreads();
        s[t] += v;
        __syncthreads();
    }
    g_cum[b * Tn + t] = s[t];
}

// ---------------- ragged gather: aligned[b,h,pos] = x[b,h,idx(pos)] * valid -------
__global__ void gather_k(const float* __restrict__ X, float* __restrict__ outAligned)
{
    __shared__ int sc[Tn];
    int b = blockIdx.y;
    int tid = threadIdx.x;
#pragma unroll
    for (int e = 0; e < 4; e++) sc[tid + 256 * e] = g_cum[b * Tn + tid + 256 * e];
    __syncthreads();

    int pos = blockIdx.x * 256 + tid;
    int total = sc[Tn - 1];
    bool valid = pos < total;
    // searchsorted(cum, pos, 'right'): first i with cum[i] > pos
    int lo = 0, hi = Tn;
    while (lo < hi) {
        int mid = (lo + hi) >> 1;
        if (sc[mid] <= pos) lo = mid + 1; else hi = mid;
    }
    int idx = min(lo, Tn - 1);

    const float* xb = X + (size_t)b * Hc * Tn;
    float* ob = outAligned + (size_t)b * Hc * MAXL + pos;
    if (valid) {
#pragma unroll 4
        for (int h = 0; h < Hc; h++) ob[(size_t)h * MAXL] = __ldg(xb + (size_t)h * Tn + idx);
    } else {
#pragma unroll 4
        for (int h = 0; h < Hc; h++) ob[(size_t)h * MAXL] = 0.f;
    }
}

// ---------------------------------------------------------------------------------
extern "C" void kernel_launch(void* const* d_in, const int* in_sizes, int n_in,
                              void* d_out, int out_size)
{
    const float* x  = (const float*)d_in[0];
    const float* W1 = (const float*)d_in[1];
    const float* b1 = (const float*)d_in[2];
    const float* g1 = (const float*)d_in[3];
    const float* be1= (const float*)d_in[4];
    const float* W2 = (const float*)d_in[5];
    const float* b2 = (const float*)d_in[6];
    const float* g2 = (const float*)d_in[7];
    const float* be2= (const float*)d_in[8];
    const float* Wl = (const float*)d_in[9];
    const float* bl = (const float*)d_in[10];

    float* out = (float*)d_out;
    float* outDur     = out;            // [B,T] durations as float
    float* outAligned = out + Bq * Tn;  // [B,H,MAXL]

    float* buf1; float* buf2;
    cudaGetSymbolAddress((void**)&buf1, g_buf1);
    cudaGetSymbolAddress((void**)&buf2, g_buf2);

    dim3 gemm_grid(Bq * (Tn / 128), Hc / 128);   // (256, 3)

    // conv1 -> buf1
    conv_gemm<<<gemm_grid, 256>>>(x, W1, b1, buf1);
    // LN1 + relu (in place)
    ln_stats<<<dim3(Tn / 256, Bq), 256>>>(buf1);
    ln_apply_relu<<<(Bq * Hc * Tn) / 256, 256>>>(buf1, g1, be1);
    // conv2 -> buf2
    conv_gemm<<<gemm_grid, 256>>>(buf1, W2, b2, buf2);
    // LN2 + relu + dot + durations (fused)
    ln_stats<<<dim3(Tn / 256, Bq), 256>>>(buf2);
    ln_dot_dur<<<dim3(Tn / 256, Bq), 256>>>(buf2, g2, be2, Wl, bl, outDur);
    // cumsum per batch
    cumsum_k<<<Bq, Tn>>>();
    // ragged gather
    gather_k<<<dim3(MAXL / 256, Bq), 256>>>(x, outAligned);
}

// round 2
// speedup vs baseline: 1.0547x; 1.0547x over previous
#include <cuda_runtime.h>
#include <math.h>

#define Bq   32
#define Hc   384
#define Tn   1024
#define MAXL 4096
#define KDIM (Hc * 3)   // 1152

// ---------------- scratch (static device arrays; no allocation) ----------------
__device__ float g_buf1[(size_t)Bq * Hc * Tn];   // conv1 out -> h1 (in-place LN)
__device__ float g_buf2[(size_t)Bq * Hc * Tn];   // conv2 out
__device__ float g_mean[Bq * Tn];
__device__ float g_rstd[Bq * Tn];
__device__ int   g_dur[Bq * Tn];
__device__ int   g_cum[Bq * Tn];

// packed f32x2 helpers (sm_100+)
__device__ __forceinline__ void fma2(unsigned long long& d, unsigned long long a,
                                     unsigned long long b)
{
    asm("fma.rn.f32x2 %0, %1, %2, %0;" : "+l"(d) : "l"(a), "l"(b));
}
__device__ __forceinline__ unsigned long long dup2(float v)
{
    unsigned long long r;
    asm("mov.b64 %0, {%1, %1};" : "=l"(r) : "f"(v));
    return r;
}
__device__ __forceinline__ void unpack2(float& lo, float& hi, unsigned long long v)
{
    asm("mov.b64 {%0, %1}, %2;" : "=f"(lo), "=f"(hi) : "l"(v));
}

// ---------------- conv-as-GEMM: Y[b,ho,t] = sum_{hi,k} W[ho,hi,k]*X[b,hi,t+k-1] + bias[ho]
// M=384 (ho), N=B*T (t fastest), K=1152 ((hi,k), k fastest)
// 128x128x8 tile, 256 threads, 8x8 per thread via packed fma.rn.f32x2 (M-paired).
__global__ __launch_bounds__(256, 2)
void conv_gemm(const float* __restrict__ X, const float* __restrict__ W,
               const float* __restrict__ bias, float* __restrict__ Y)
{
    const int tid = threadIdx.x;
    const int b   = blockIdx.x >> 3;
    const int t0  = (blockIdx.x & 7) << 7;   // 128-wide t tile
    const int m0  = blockIdx.y << 7;         // 128-wide ho tile

    __shared__ __align__(16) float As[2][8][128];
    __shared__ __align__(16) float Bs[2][8][128];

    // acc2[j][i2]: j = B-col 0..7, i2 = A-row-pair 0..3 (lo = row 2*i2, hi = row 2*i2+1)
    unsigned long long acc2[8][4];
#pragma unroll
    for (int j = 0; j < 8; j++)
#pragma unroll
        for (int i2 = 0; i2 < 4; i2++) acc2[j][i2] = 0ULL;

    const int tx = tid & 15;
    const int ty = tid >> 4;

    const float* Xb = X + (size_t)b * Hc * Tn;

    // initial tile (ks = 0)
#pragma unroll
    for (int e = 0; e < 4; e++) {
        int idx = tid + 256 * e;
        int arow = idx >> 3, akk = idx & 7;
        As[0][akk][arow] = W[(size_t)(m0 + arow) * KDIM + akk];
        int bkk = idx >> 7, bcol = idx & 127;
        int hi = bkk / 3, kr = bkk - hi * 3;
        int t = t0 + bcol + kr - 1;
        Bs[0][bkk][bcol] = ((unsigned)t < (unsigned)Tn) ? Xb[hi * Tn + t] : 0.f;
    }
    __syncthreads();

    int buf = 0;
    for (int ks = 8; ks < KDIM; ks += 8) {
        float ra[4], rb[4];
#pragma unroll
        for (int e = 0; e < 4; e++) {
            int idx = tid + 256 * e;
            int arow = idx >> 3, akk = idx & 7;
            ra[e] = W[(size_t)(m0 + arow) * KDIM + ks + akk];
            int bkk = idx >> 7, bcol = idx & 127;
            int kidx = ks + bkk;
            int hi = kidx / 3, kr = kidx - hi * 3;
            int t = t0 + bcol + kr - 1;
            rb[e] = ((unsigned)t < (unsigned)Tn) ? Xb[hi * Tn + t] : 0.f;
        }
#pragma unroll
        for (int kk = 0; kk < 8; kk++) {
            ulonglong2 a01 = *(const ulonglong2*)&As[buf][kk][ty * 8];
            ulonglong2 a23 = *(const ulonglong2*)&As[buf][kk][ty * 8 + 4];
            unsigned long long ap[4] = {a01.x, a01.y, a23.x, a23.y};
            float4 b0 = *(const float4*)&Bs[buf][kk][tx * 8];
            float4 b1 = *(const float4*)&Bs[buf][kk][tx * 8 + 4];
            float bv[8] = {b0.x, b0.y, b0.z, b0.w, b1.x, b1.y, b1.z, b1.w};
#pragma unroll
            for (int j = 0; j < 8; j++) {
                unsigned long long bd = dup2(bv[j]);
#pragma unroll
                for (int i2 = 0; i2 < 4; i2++) fma2(acc2[j][i2], ap[i2], bd);
            }
        }
#pragma unroll
        for (int e = 0; e < 4; e++) {
            int idx = tid + 256 * e;
            As[buf ^ 1][idx & 7][idx >> 3] = ra[e];
            Bs[buf ^ 1][idx >> 7][idx & 127] = rb[e];
        }
        __syncthreads();
        buf ^= 1;
    }
    // last tile
#pragma unroll
    for (int kk = 0; kk < 8; kk++) {
        ulonglong2 a01 = *(const ulonglong2*)&As[buf][kk][ty * 8];
        ulonglong2 a23 = *(const ulonglong2*)&As[buf][kk][ty * 8 + 4];
        unsigned long long ap[4] = {a01.x, a01.y, a23.x, a23.y};
        float4 b0 = *(const float4*)&Bs[buf][kk][tx * 8];
        float4 b1 = *(const float4*)&Bs[buf][kk][tx * 8 + 4];
        float bv[8] = {b0.x, b0.y, b0.z, b0.w, b1.x, b1.y, b1.z, b1.w};
#pragma unroll
        for (int j = 0; j < 8; j++) {
            unsigned long long bd = dup2(bv[j]);
#pragma unroll
            for (int i2 = 0; i2 < 4; i2++) fma2(acc2[j][i2], ap[i2], bd);
        }
    }

    // epilogue: unpack, + bias, store (two rows per i2)
#pragma unroll
    for (int i2 = 0; i2 < 4; i2++) {
        int r0 = m0 + ty * 8 + 2 * i2;
        float bi0 = bias[r0];
        float bi1 = bias[r0 + 1];
        float lo[8], hi[8];
#pragma unroll
        for (int j = 0; j < 8; j++) unpack2(lo[j], hi[j], acc2[j][i2]);
        float* yp0 = Y + ((size_t)b * Hc + r0) * Tn + t0 + tx * 8;
        float* yp1 = yp0 + Tn;
        *(float4*)yp0       = make_float4(lo[0] + bi0, lo[1] + bi0, lo[2] + bi0, lo[3] + bi0);
        *(float4*)(yp0 + 4) = make_float4(lo[4] + bi0, lo[5] + bi0, lo[6] + bi0, lo[7] + bi0);
        *(float4*)yp1       = make_float4(hi[0] + bi1, hi[1] + bi1, hi[2] + bi1, hi[3] + bi1);
        *(float4*)(yp1 + 4) = make_float4(hi[4] + bi1, hi[5] + bi1, hi[6] + bi1, hi[7] + bi1);
    }
}

// ---------------- LN stats over channel dim: one thread per (b,t) ----------------
__global__ void ln_stats(const float* __restrict__ Y)
{
    int b = blockIdx.y;
    int t = blockIdx.x * 256 + threadIdx.x;
    const float* p = Y + (size_t)b * Hc * Tn + t;
    float s = 0.f, s2 = 0.f;
#pragma unroll 8
    for (int h = 0; h < Hc; h++) {
        float v = __ldg(p + (size_t)h * Tn);
        s += v; s2 += v * v;
    }
    float m = s * (1.f / Hc);
    float var = s2 * (1.f / Hc) - m * m;
    g_mean[b * Tn + t] = m;
    g_rstd[b * Tn + t] = rsqrtf(var + 1e-5f);
}

// ---------------- LN apply + relu (elementwise, in-place) ----------------
__global__ void ln_apply_relu(float* __restrict__ Y,
                              const float* __restrict__ g, const float* __restrict__ be)
{
    int i = blockIdx.x * 256 + threadIdx.x;
    int t = i & (Tn - 1);
    int bh = i >> 10;
    int h = bh % Hc;
    int b = bh / Hc;
    float v = (Y[i] - g_mean[b * Tn + t]) * g_rstd[b * Tn + t] * __ldg(g + h) + __ldg(be + h);
    Y[i] = fmaxf(v, 0.f);
}

// ---------------- LN2 + relu + dot(Wl) + duration, fused ----------------
__global__ void ln_dot_dur(const float* __restrict__ Y2,
                           const float* __restrict__ g, const float* __restrict__ be,
                           const float* __restrict__ Wl, const float* __restrict__ bl,
                           float* __restrict__ durF)
{
    int b = blockIdx.y;
    int t = blockIdx.x * 256 + threadIdx.x;
    const float* p = Y2 + (size_t)b * Hc * Tn + t;
    float m = g_mean[b * Tn + t];
    float r = g_rstd[b * Tn + t];
    float acc = 0.f;
#pragma unroll 8
    for (int h = 0; h < Hc; h++) {
        float v = (__ldg(p + (size_t)h * Tn) - m) * r * __ldg(g + h) + __ldg(be + h);
        acc += fmaxf(v, 0.f) * __ldg(Wl + h);
    }
    float z = fmaxf(acc + __ldg(bl), 0.f);
    int d = (int)floorf(expf(z));
    g_dur[b * Tn + t] = d;
    durF[b * Tn + t] = (float)d;
}

// ---------------- per-batch inclusive cumsum (T=1024, Hillis-Steele) ----------------
__global__ void cumsum_k()
{
    __shared__ int s[Tn];
    int b = blockIdx.x, t = threadIdx.x;
    s[t] = g_dur[b * Tn + t];
    __syncthreads();
#pragma unroll
    for (int off = 1; off < Tn; off <<= 1) {
        int v = (t >= off) ? s[t - off] : 0;
        __syncthreads();
        s[t] += v;
        __syncthreads();
    }
    g_cum[b * Tn + t] = s[t];
}

// ---------------- ragged gather: aligned[b,h,pos] = x[b,h,idx(pos)] * valid -------
__global__ void gather_k(const float* __restrict__ X, float* __restrict__ outAligned)
{
    __shared__ int sc[Tn];
    int b = blockIdx.y;
    int tid = threadIdx.x;
#pragma unroll
    for (int e = 0; e < 4; e++) sc[tid + 256 * e] = g_cum[b * Tn + tid + 256 * e];
    __syncthreads();

    int pos = blockIdx.x * 256 + tid;
    int total = sc[Tn - 1];
    bool valid = pos < total;
    int lo = 0, hi = Tn;
    while (lo < hi) {
        int mid = (lo + hi) >> 1;
        if (sc[mid] <= pos) lo = mid + 1; else hi = mid;
    }
    int idx = min(lo, Tn - 1);

    const float* xb = X + (size_t)b * Hc * Tn;
    float* ob = outAligned + (size_t)b * Hc * MAXL + pos;
    if (valid) {
#pragma unroll 4
        for (int h = 0; h < Hc; h++) ob[(size_t)h * MAXL] = __ldg(xb + (size_t)h * Tn + idx);
    } else {
#pragma unroll 4
        for (int h = 0; h < Hc; h++) ob[(size_t)h * MAXL] = 0.f;
    }
}

// ---------------------------------------------------------------------------------
extern "C" void kernel_launch(void* const* d_in, const int* in_sizes, int n_in,
                              void* d_out, int out_size)
{
    const float* x  = (const float*)d_in[0];
    const float* W1 = (const float*)d_in[1];
    const float* b1 = (const float*)d_in[2];
    const float* g1 = (const float*)d_in[3];
    const float* be1= (const float*)d_in[4];
    const float* W2 = (const float*)d_in[5];
    const float* b2 = (const float*)d_in[6];
    const float* g2 = (const float*)d_in[7];
    const float* be2= (const float*)d_in[8];
    const float* Wl = (const float*)d_in[9];
    const float* bl = (const float*)d_in[10];

    float* out = (float*)d_out;
    float* outDur     = out;            // [B,T] durations as float
    float* outAligned = out + Bq * Tn;  // [B,H,MAXL]

    float* buf1; float* buf2;
    cudaGetSymbolAddress((void**)&buf1, g_buf1);
    cudaGetSymbolAddress((void**)&buf2, g_buf2);

    dim3 gemm_grid(Bq * (Tn / 128), Hc / 128);   // (256, 3)

    conv_gemm<<<gemm_grid, 256>>>(x, W1, b1, buf1);
    ln_stats<<<dim3(Tn / 256, Bq), 256>>>(buf1);
    ln_apply_relu<<<(Bq * Hc * Tn) / 256, 256>>>(buf1, g1, be1);
    conv_gemm<<<gemm_grid, 256>>>(buf1, W2, b2, buf2);
    ln_stats<<<dim3(Tn / 256, Bq), 256>>>(buf2);
    ln_dot_dur<<<dim3(Tn / 256, Bq), 256>>>(buf2, g2, be2, Wl, bl, outDur);
    cumsum_k<<<Bq, Tn>>>();
    gather_k<<<dim3(MAXL / 256, Bq), 256>>>(x, outAligned);
}

// round 4
// speedup vs baseline: 1.1659x; 1.1055x over previous
#include <cuda_runtime.h>
#include <math.h>
#include <stdint.h>

#define Bq   32
#define Hc   384
#define Tn   1024
#define MAXL 4096
#define NBLK 512               // T/2 winograd blocks per batch
#define NTOT (Bq * NBLK)       // 16384 GEMM columns

// ---------------- scratch ----------------
__device__ float g_buf1[(size_t)Bq * Hc * Tn];
__device__ float g_buf2[(size_t)Bq * Hc * Tn];
__device__ float g_M[4][Hc][NTOT];          // phase GEMM outputs (100MB)
__device__ float g_U[2][4][Hc * Hc];        // transformed weights per conv
__device__ float g_mean[Bq * Tn];
__device__ float g_rstd[Bq * Tn];
__device__ int   g_dur[Bq * Tn];
__device__ int   g_cum[Bq * Tn];

// packed f32x2 helpers (sm_100+)
__device__ __forceinline__ void fma2(unsigned long long& d, unsigned long long a,
                                     unsigned long long b)
{
    asm("fma.rn.f32x2 %0, %1, %2, %0;" : "+l"(d) : "l"(a), "l"(b));
}
__device__ __forceinline__ unsigned long long dup2(float v)
{
    unsigned long long r;
    asm("mov.b64 %0, {%1, %1};" : "=l"(r) : "f"(v));
    return r;
}
__device__ __forceinline__ void unpack2(float& lo, float& hi, unsigned long long v)
{
    asm("mov.b64 {%0, %1}, %2;" : "=f"(lo), "=f"(hi) : "l"(v));
}

// ---------------- weight transform: U_p[ho][hi] from W[ho][hi][3] ----------------
__global__ void wino_wt(const float* __restrict__ W, float* __restrict__ U)
{
    int idx = blockIdx.x * 256 + threadIdx.x;     // 147456
    float g0 = W[idx * 3 + 0];
    float g1 = W[idx * 3 + 1];
    float g2 = W[idx * 3 + 2];
    U[0 * Hc * Hc + idx] = g0;
    U[1 * Hc * Hc + idx] = 0.5f * (g0 + g1 + g2);
    U[2 * Hc * Hc + idx] = 0.5f * (g0 - g1 + g2);
    U[3 * Hc * Hc + idx] = g2;
}

// ---------------- phase GEMM: M_p[ho][n] = sum_hi U_p[ho][hi] * V_p[hi][n]
// V_p computed on the fly from X:  (block nb, d_i = x[2nb-1 .. 2nb+2])
//  p0: d0-d2   p1: d1+d2   p2: d2-d1   p3: d1-d3
// 128x128x8 tile, 256 threads, 8x8 per thread via fma.rn.f32x2 (M-row pairs).
__global__ __launch_bounds__(256, 2)
void wino_gemm(const float* __restrict__ X, const float* __restrict__ Ubase,
               float* __restrict__ M)
{
    const int tid = threadIdx.x;
    const int b   = blockIdx.x >> 2;
    const int nb0 = (blockIdx.x & 3) << 7;   // 128-wide block tile
    const int m0  = blockIdx.y << 7;         // 128-wide ho tile
    const int p   = blockIdx.z;              // phase 0..3

    const float* U = Ubase + (size_t)p * Hc * Hc;
    const float* Xb = X + (size_t)b * Hc * Tn;

    __shared__ __align__(16) float As[2][8][128];
    __shared__ __align__(16) float Bs[2][8][128];

    unsigned long long acc2[8][4];
#pragma unroll
    for (int j = 0; j < 8; j++)
#pragma unroll
        for (int i2 = 0; i2 < 4; i2++) acc2[j][i2] = 0ULL;

    const int tx = tid & 15;
    const int ty = tid >> 4;

    // B-fill helper: V_p element for row hi, block nb (local col)
    auto vfill = [&](int hi, int nbl) -> float {
        const float* xp = Xb + (size_t)hi * Tn;
        int t2 = 2 * (nb0 + nbl);
        float d1 = xp[t2];
        float d2 = xp[t2 + 1];
        if (p == 0) {
            float d0 = (t2 > 0) ? xp[t2 - 1] : 0.f;
            return d0 - d2;
        } else if (p == 1) {
            return d1 + d2;
        } else if (p == 2) {
            return d2 - d1;
        } else {
            float d3 = (t2 + 2 < Tn) ? xp[t2 + 2] : 0.f;
            return d1 - d3;
        }
    };

    // initial tile (ks = 0)
#pragma unroll
    for (int e = 0; e < 4; e++) {
        int idx = tid + 256 * e;
        int arow = idx >> 3, akk = idx & 7;
        As[0][akk][arow] = U[(size_t)(m0 + arow) * Hc + akk];
        int bkk = idx >> 7, bcol = idx & 127;
        Bs[0][bkk][bcol] = vfill(bkk, bcol);
    }
    __syncthreads();

    int buf = 0;
    for (int ks = 8; ks < Hc; ks += 8) {
        float ra[4], rb[4];
#pragma unroll
        for (int e = 0; e < 4; e++) {
            int idx = tid + 256 * e;
            int arow = idx >> 3, akk = idx & 7;
            ra[e] = U[(size_t)(m0 + arow) * Hc + ks + akk];
            int bkk = idx >> 7, bcol = idx & 127;
            rb[e] = vfill(ks + bkk, bcol);
        }
#pragma unroll
        for (int kk = 0; kk < 8; kk++) {
            ulonglong2 a01 = *(const ulonglong2*)&As[buf][kk][ty * 8];
            ulonglong2 a23 = *(const ulonglong2*)&As[buf][kk][ty * 8 + 4];
            unsigned long long ap[4] = {a01.x, a01.y, a23.x, a23.y};
            float4 b0 = *(const float4*)&Bs[buf][kk][tx * 8];
            float4 b1 = *(const float4*)&Bs[buf][kk][tx * 8 + 4];
            float bv[8] = {b0.x, b0.y, b0.z, b0.w, b1.x, b1.y, b1.z, b1.w};
#pragma unroll
            for (int j = 0; j < 8; j++) {
                unsigned long long bd = dup2(bv[j]);
#pragma unroll
                for (int i2 = 0; i2 < 4; i2++) fma2(acc2[j][i2], ap[i2], bd);
            }
        }
#pragma unroll
        for (int e = 0; e < 4; e++) {
            int idx = tid + 256 * e;
            As[buf ^ 1][idx & 7][idx >> 3] = ra[e];
            Bs[buf ^ 1][idx >> 7][idx & 127] = rb[e];
        }
        __syncthreads();
        buf ^= 1;
    }
#pragma unroll
    for (int kk = 0; kk < 8; kk++) {
        ulonglong2 a01 = *(const ulonglong2*)&As[buf][kk][ty * 8];
        ulonglong2 a23 = *(const ulonglong2*)&As[buf][kk][ty * 8 + 4];
        unsigned long long ap[4] = {a01.x, a01.y, a23.x, a23.y};
        float4 b0 = *(const float4*)&Bs[buf][kk][tx * 8];
        float4 b1 = *(const float4*)&Bs[buf][kk][tx * 8 + 4];
        float bv[8] = {b0.x, b0.y, b0.z, b0.w, b1.x, b1.y, b1.z, b1.w};
#pragma unroll
        for (int j = 0; j < 8; j++) {
            unsigned long long bd = dup2(bv[j]);
#pragma unroll
            for (int i2 = 0; i2 < 4; i2++) fma2(acc2[j][i2], ap[i2], bd);
        }
    }

    // store to M[p][ho][b*512 + nb0 + ...]
#pragma unroll
    for (int i2 = 0; i2 < 4; i2++) {
        int r0 = m0 + ty * 8 + 2 * i2;
        float lo[8], hi[8];
#pragma unroll
        for (int j = 0; j < 8; j++) unpack2(lo[j], hi[j], acc2[j][i2]);
        float* mp0 = M + ((size_t)p * Hc + r0) * NTOT + b * NBLK + nb0 + tx * 8;
        float* mp1 = mp0 + NTOT;
        *(float4*)mp0       = make_float4(lo[0], lo[1], lo[2], lo[3]);
        *(float4*)(mp0 + 4) = make_float4(lo[4], lo[5], lo[6], lo[7]);
        *(float4*)mp1       = make_float4(hi[0], hi[1], hi[2], hi[3]);
        *(float4*)(mp1 + 4) = make_float4(hi[4], hi[5], hi[6], hi[7]);
    }
}

// ---------------- output transform: y(2t)=M1+M2+M3+b, y(2t+1)=M2-M3-M4+b --------
__global__ void wino_out(const float* __restrict__ M, const float* __restrict__ bias,
                         float* __restrict__ Y)
{
    int i = blockIdx.x * 256 + threadIdx.x;       // over b*Hc*NBLK = 6.29M
    int nb = i & (NBLK - 1);
    int tmp = i >> 9;
    int ho = tmp % Hc;
    int b = tmp / Hc;
    size_t col = (size_t)b * NBLK + nb;
    const float* mp = M + (size_t)ho * NTOT + col;
    float m1 = mp[0];
    float m2 = mp[(size_t)Hc * NTOT];
    float m3 = mp[2 * (size_t)Hc * NTOT];
    float m4 = mp[3 * (size_t)Hc * NTOT];
    float bi = __ldg(bias + ho);
    float2 y = make_float2(m1 + m2 + m3 + bi, m2 - m3 - m4 + bi);
    *(float2*)(Y + ((size_t)b * Hc + ho) * Tn + 2 * nb) = y;
}

// ---------------- LN stats over channel dim ----------------
__global__ void ln_stats(const float* __restrict__ Y)
{
    int b = blockIdx.y;
    int t = blockIdx.x * 256 + threadIdx.x;
    const float* p = Y + (size_t)b * Hc * Tn + t;
    float s = 0.f, s2 = 0.f;
#pragma unroll 8
    for (int h = 0; h < Hc; h++) {
        float v = __ldg(p + (size_t)h * Tn);
        s += v; s2 += v * v;
    }
    float m = s * (1.f / Hc);
    float var = s2 * (1.f / Hc) - m * m;
    g_mean[b * Tn + t] = m;
    g_rstd[b * Tn + t] = rsqrtf(var + 1e-5f);
}

__global__ void ln_apply_relu(float* __restrict__ Y,
                              const float* __restrict__ g, const float* __restrict__ be)
{
    int i = blockIdx.x * 256 + threadIdx.x;
    int t = i & (Tn - 1);
    int bh = i >> 10;
    int h = bh % Hc;
    int b = bh / Hc;
    float v = (Y[i] - g_mean[b * Tn + t]) * g_rstd[b * Tn + t] * __ldg(g + h) + __ldg(be + h);
    Y[i] = fmaxf(v, 0.f);
}

__global__ void ln_dot_dur(const float* __restrict__ Y2,
                           const float* __restrict__ g, const float* __restrict__ be,
                           const float* __restrict__ Wl, const float* __restrict__ bl,
                           float* __restrict__ durF)
{
    int b = blockIdx.y;
    int t = blockIdx.x * 256 + threadIdx.x;
    const float* p = Y2 + (size_t)b * Hc * Tn + t;
    float m = g_mean[b * Tn + t];
    float r = g_rstd[b * Tn + t];
    float acc = 0.f;
#pragma unroll 8
    for (int h = 0; h < Hc; h++) {
        float v = (__ldg(p + (size_t)h * Tn) - m) * r * __ldg(g + h) + __ldg(be + h);
        acc += fmaxf(v, 0.f) * __ldg(Wl + h);
    }
    float z = fmaxf(acc + __ldg(bl), 0.f);
    int d = (int)floorf(expf(z));
    g_dur[b * Tn + t] = d;
    durF[b * Tn + t] = (float)d;
}

__global__ void cumsum_k()
{
    __shared__ int s[Tn];
    int b = blockIdx.x, t = threadIdx.x;
    s[t] = g_dur[b * Tn + t];
    __syncthreads();
#pragma unroll
    for (int off = 1; off < Tn; off <<= 1) {
        int v = (t >= off) ? s[t - off] : 0;
        __syncthreads();
        s[t] += v;
        __syncthreads();
    }
    g_cum[b * Tn + t] = s[t];
}

__global__ void gather_k(const float* __restrict__ X, float* __restrict__ outAligned)
{
    __shared__ int sc[Tn];
    int b = blockIdx.y;
    int tid = threadIdx.x;
#pragma unroll
    for (int e = 0; e < 4; e++) sc[tid + 256 * e] = g_cum[b * Tn + tid + 256 * e];
    __syncthreads();

    int pos = blockIdx.x * 256 + tid;
    int total = sc[Tn - 1];
    bool valid = pos < total;
    int lo = 0, hi = Tn;
    while (lo < hi) {
        int mid = (lo + hi) >> 1;
        if (sc[mid] <= pos) lo = mid + 1; else hi = mid;
    }
    int idx = min(lo, Tn - 1);

    const float* xb = X + (size_t)b * Hc * Tn;
    float* ob = outAligned + (size_t)b * Hc * MAXL + pos;
    if (valid) {
#pragma unroll 4
        for (int h = 0; h < Hc; h++) ob[(size_t)h * MAXL] = __ldg(xb + (size_t)h * Tn + idx);
    } else {
#pragma unroll 4
        for (int h = 0; h < Hc; h++) ob[(size_t)h * MAXL] = 0.f;
    }
}

// ---------------------------------------------------------------------------------
extern "C" void kernel_launch(void* const* d_in, const int* in_sizes, int n_in,
                              void* d_out, int out_size)
{
    const float* x  = (const float*)d_in[0];
    const float* W1 = (const float*)d_in[1];
    const float* b1 = (const float*)d_in[2];
    const float* g1 = (const float*)d_in[3];
    const float* be1= (const float*)d_in[4];
    const float* W2 = (const float*)d_in[5];
    const float* b2 = (const float*)d_in[6];
    const float* g2 = (const float*)d_in[7];
    const float* be2= (const float*)d_in[8];
    const float* Wl = (const float*)d_in[9];
    const float* bl = (const float*)d_in[10];

    float* out = (float*)d_out;
    float* outDur     = out;
    float* outAligned = out + Bq * Tn;

    float *buf1, *buf2, *Mbuf, *Ubuf;
    cudaGetSymbolAddress((void**)&buf1, g_buf1);
    cudaGetSymbolAddress((void**)&buf2, g_buf2);
    cudaGetSymbolAddress((void**)&Mbuf, g_M);
    cudaGetSymbolAddress((void**)&Ubuf, g_U);
    float* U1 = Ubuf;
    float* U2 = Ubuf + 4 * Hc * Hc;

    dim3 gemm_grid(Bq * (NBLK / 128), Hc / 128, 4);   // (128, 3, 4)
    dim3 ln_grid(Tn / 256, Bq);

    wino_wt<<<(Hc * Hc) / 256, 256>>>(W1, U1);
    wino_wt<<<(Hc * Hc) / 256, 256>>>(W2, U2);

    // conv1
    wino_gemm<<<gemm_grid, 256>>>(x, U1, Mbuf);
    wino_out<<<(Bq * Hc * NBLK) / 256, 256>>>(Mbuf, b1, buf1);
    ln_stats<<<ln_grid, 256>>>(buf1);
    ln_apply_relu<<<(Bq * Hc * Tn) / 256, 256>>>(buf1, g1, be1);
    // conv2
    wino_gemm<<<gemm_grid, 256>>>(buf1, U2, Mbuf);
    wino_out<<<(Bq * Hc * NBLK) / 256, 256>>>(Mbuf, b2, buf2);
    ln_stats<<<ln_grid, 256>>>(buf2);
    ln_dot_dur<<<ln_grid, 256>>>(buf2, g2, be2, Wl, bl, outDur);

    cumsum_k<<<Bq, Tn>>>();
    gather_k<<<dim3(MAXL / 256, Bq), 256>>>(x, outAligned);
}

// round 5
// speedup vs baseline: 1.9884x; 1.7054x over previous
#include <cuda_runtime.h>
#include <math.h>
#include <stdint.h>

#define Bq   32
#define Hc   384
#define Tn   1024
#define MAXL 4096
#define NBLK 512               // T/2 winograd blocks per batch
#define NTOT (Bq * NBLK)       // 16384 GEMM columns (m-dim)
#define KT   48                // 384/8 k-chunks
#define MT   (NTOT / 16)       // 1024 m-tiles
#define NT   48                // 384/8 n-tiles (ho)

// ---------------- scratch ----------------
__device__ float g_buf1[(size_t)Bq * Hc * Tn];
__device__ float g_buf2[(size_t)Bq * Hc * Tn];
__device__ float g_M[4][Hc][NTOT];                       // phase GEMM outputs
__device__ float g_Vf[(size_t)4 * 2 * KT * MT * 128];    // A frags [p][h][kt][mt][lane][4]
__device__ float g_Bf[2][4 * 2 * KT * NT * 64];          // B frags [conv][p][h][kt][nt][lane][2]
__device__ float g_mean[Bq * Tn];
__device__ float g_rstd[Bq * Tn];
__device__ int   g_dur[Bq * Tn];
__device__ int   g_cum[Bq * Tn];

__device__ __forceinline__ uint32_t f2tf32(float x)
{
    uint32_t r;
    asm("cvt.rna.tf32.f32 %0, %1;" : "=r"(r) : "f"(x));
    return r;
}
__device__ __forceinline__ void tf32_split(float x, float& h, float& l)
{
    uint32_t hb = f2tf32(x);
    h = __uint_as_float(hb);
    l = __uint_as_float(f2tf32(x - h));
}

#define MMA_TF32(c, a, b) \
    asm volatile("mma.sync.aligned.m16n8k8.row.col.f32.tf32.tf32.f32 " \
        "{%0,%1,%2,%3}, {%4,%5,%6,%7}, {%8,%9}, {%0,%1,%2,%3};" \
        : "+f"((c)[0]), "+f"((c)[1]), "+f"((c)[2]), "+f"((c)[3]) \
        : "r"(__float_as_uint((a).x)), "r"(__float_as_uint((a).y)), \
          "r"(__float_as_uint((a).z)), "r"(__float_as_uint((a).w)), \
          "r"(__float_as_uint((b).x)), "r"(__float_as_uint((b).y)))

// ---------------- V prep: X -> A fragments (frag-major, tf32 hi/lo) ----------------
// element (m, k): m = GEMM col (b*512+nb), k = hi channel.
// V0=d0-d2, V1=d1+d2, V2=d2-d1, V3=d1-d3 with d_i = x[2nb-1+i].
// Frag slot s of lane (g=lane>>2, t=lane&3): s0=(g,t) s1=(g+8,t) s2=(g,t+4) s3=(g+8,t+4)
__global__ void vprep(const float* __restrict__ X, float* __restrict__ Af)
{
    int gw = blockIdx.x * 8 + (threadIdx.x >> 5);   // warp per (kt, mt)
    int lane = threadIdx.x & 31;
    int kt = gw >> 10;
    int mt = gw & 1023;
    int g = lane >> 2, t4 = lane & 3;

    float4 outv[4][2];
#pragma unroll
    for (int s = 0; s < 4; s++) {
        int r  = g + ((s & 1) ? 8 : 0);
        int kk = t4 + ((s & 2) ? 4 : 0);
        int m = mt * 16 + r;
        int b = m >> 9, nb = m & 511;
        int hi = kt * 8 + kk;
        const float* xp = X + ((size_t)b * Hc + hi) * Tn;
        int t2 = 2 * nb;
        float d0 = (t2 > 0) ? __ldg(xp + t2 - 1) : 0.f;
        float d1 = __ldg(xp + t2);
        float d2 = __ldg(xp + t2 + 1);
        float d3 = (t2 + 2 < Tn) ? __ldg(xp + t2 + 2) : 0.f;
        float v[4] = {d0 - d2, d1 + d2, d2 - d1, d1 - d3};
#pragma unroll
        for (int p = 0; p < 4; p++) {
            float h, l;
            tf32_split(v[p], h, l);
            ((float*)&outv[p][0])[s] = h;
            ((float*)&outv[p][1])[s] = l;
        }
    }
#pragma unroll
    for (int p = 0; p < 4; p++)
#pragma unroll
        for (int h = 0; h < 2; h++)
            *(float4*)(Af + ((((size_t)(p * 2 + h) * KT + kt) * MT + mt) * 128) + lane * 4)
                = outv[p][h];
}

// ---------------- B prep: W -> U_p fragments (frag-major, tf32 hi/lo) -------------
// b0 = (k=t, n=g), b1 = (k=t+4, n=g);  n = ho, k = hi.
__global__ void bprep(const float* __restrict__ W, float* __restrict__ Bf)
{
    int gw = blockIdx.x * 8 + (threadIdx.x >> 5);   // warp per (kt, nt); 2304 warps
    int lane = threadIdx.x & 31;
    int kt = gw / NT, nt = gw % NT;
    int g = lane >> 2, t4 = lane & 3;
    int ho = nt * 8 + g;

    float2 outv[4][2];
#pragma unroll
    for (int s = 0; s < 2; s++) {
        int hi = kt * 8 + t4 + s * 4;
        const float* wp = W + ((size_t)ho * Hc + hi) * 3;
        float g0 = __ldg(wp), g1 = __ldg(wp + 1), g2 = __ldg(wp + 2);
        float u[4] = {g0, 0.5f * (g0 + g1 + g2), 0.5f * (g0 - g1 + g2), g2};
#pragma unroll
        for (int p = 0; p < 4; p++) {
            float h, l;
            tf32_split(u[p], h, l);
            ((float*)&outv[p][0])[s] = h;
            ((float*)&outv[p][1])[s] = l;
        }
    }
#pragma unroll
    for (int p = 0; p < 4; p++)
#pragma unroll
        for (int h = 0; h < 2; h++)
            *(float2*)(Bf + ((((size_t)(p * 2 + h) * KT + kt) * NT + nt) * 64) + lane * 2)
                = outv[p][h];
}

// ---------------- phase GEMM on tensor cores: M_p[ho][m] = sum_k V.U ----------------
// CTA tile 128(m) x 128(ho); 8 warps as 4(m) x 2(n); warp tile 32m x 64n = 2x8 mma tiles.
// 3xTF32: AhBh + AhBl + AlBh per position -> 48 mma / warp / kt.
__global__ __launch_bounds__(256, 1)
void wino_mma(const float* __restrict__ Af, const float* __restrict__ Bf,
              float* __restrict__ M)
{
    const int p = blockIdx.z, mc = blockIdx.x, nc = blockIdx.y;
    const int w = threadIdx.x >> 5, lane = threadIdx.x & 31;
    const int wm = w & 3, wn = w >> 2;
    const int mt0 = mc * 8 + wm * 2;
    const int nt0 = nc * 16 + wn * 8;

    float c[16][4];
#pragma unroll
    for (int i = 0; i < 16; i++)
#pragma unroll
        for (int r = 0; r < 4; r++) c[i][r] = 0.f;

    const float* Abase[2] = {
        Af + (size_t)(p * 2 + 0) * KT * MT * 128,
        Af + (size_t)(p * 2 + 1) * KT * MT * 128 };
    const float* Bbase[2] = {
        Bf + (size_t)(p * 2 + 0) * KT * NT * 64,
        Bf + (size_t)(p * 2 + 1) * KT * NT * 64 };

#pragma unroll 2
    for (int kt = 0; kt < KT; kt++) {
        float4 a[2][2];
#pragma unroll
        for (int i = 0; i < 2; i++)
#pragma unroll
            for (int h = 0; h < 2; h++)
                a[i][h] = __ldg((const float4*)(Abase[h]
                            + (((size_t)kt * MT + mt0 + i) * 128) + lane * 4));
        float2 b[8][2];
#pragma unroll
        for (int j = 0; j < 8; j++)
#pragma unroll
            for (int h = 0; h < 2; h++)
                b[j][h] = __ldg((const float2*)(Bbase[h]
                            + (((size_t)kt * NT + nt0 + j) * 64) + lane * 2));
#pragma unroll
        for (int i = 0; i < 2; i++)
#pragma unroll
            for (int j = 0; j < 8; j++) {
                MMA_TF32(c[i * 8 + j], a[i][0], b[j][0]);
                MMA_TF32(c[i * 8 + j], a[i][0], b[j][1]);
                MMA_TF32(c[i * 8 + j], a[i][1], b[j][0]);
            }
    }

    // store C frags -> M[p][ho][m]
    const int g = lane >> 2, t4 = lane & 3;
#pragma unroll
    for (int i = 0; i < 2; i++)
#pragma unroll
        for (int j = 0; j < 8; j++) {
            int m  = mc * 128 + wm * 32 + i * 16 + g;
            int ho = nc * 128 + wn * 64 + j * 8 + 2 * t4;
            float* mp = M + ((size_t)p * Hc + ho) * NTOT + m;
            mp[0]        = c[i * 8 + j][0];   // (g,   2t)
            mp[NTOT]     = c[i * 8 + j][1];   // (g,   2t+1)
            mp[8]        = c[i * 8 + j][2];   // (g+8, 2t)
            mp[NTOT + 8] = c[i * 8 + j][3];   // (g+8, 2t+1)
        }
}

// ---------------- output transform: y(2t)=M1+M2+M3+b, y(2t+1)=M2-M3-M4+b --------
__global__ void wino_out(const float* __restrict__ M, const float* __restrict__ bias,
                         float* __restrict__ Y)
{
    int i = blockIdx.x * 256 + threadIdx.x;
    int nb = i & (NBLK - 1);
    int tmp = i >> 9;
    int ho = tmp % Hc;
    int b = tmp / Hc;
    size_t col = (size_t)b * NBLK + nb;
    const float* mp = M + (size_t)ho * NTOT + col;
    float m1 = mp[0];
    float m2 = mp[(size_t)Hc * NTOT];
    float m3 = mp[2 * (size_t)Hc * NTOT];
    float m4 = mp[3 * (size_t)Hc * NTOT];
    float bi = __ldg(bias + ho);
    float2 y = make_float2(m1 + m2 + m3 + bi, m2 - m3 - m4 + bi);
    *(float2*)(Y + ((size_t)b * Hc + ho) * Tn + 2 * nb) = y;
}

// ---------------- LN stats over channel dim ----------------
__global__ void ln_stats(const float* __restrict__ Y)
{
    int b = blockIdx.y;
    int t = blockIdx.x * 256 + threadIdx.x;
    const float* p = Y + (size_t)b * Hc * Tn + t;
    float s = 0.f, s2 = 0.f;
#pragma unroll 8
    for (int h = 0; h < Hc; h++) {
        float v = __ldg(p + (size_t)h * Tn);
        s += v; s2 += v * v;
    }
    float m = s * (1.f / Hc);
    float var = s2 * (1.f / Hc) - m * m;
    g_mean[b * Tn + t] = m;
    g_rstd[b * Tn + t] = rsqrtf(var + 1e-5f);
}

__global__ void ln_apply_relu(float* __restrict__ Y,
                              const float* __restrict__ g, const float* __restrict__ be)
{
    int i = blockIdx.x * 256 + threadIdx.x;
    int t = i & (Tn - 1);
    int bh = i >> 10;
    int h = bh % Hc;
    int b = bh / Hc;
    float v = (Y[i] - g_mean[b * Tn + t]) * g_rstd[b * Tn + t] * __ldg(g + h) + __ldg(be + h);
    Y[i] = fmaxf(v, 0.f);
}

__global__ void ln_dot_dur(const float* __restrict__ Y2,
                           const float* __restrict__ g, const float* __restrict__ be,
                           const float* __restrict__ Wl, const float* __restrict__ bl,
                           float* __restrict__ durF)
{
    int b = blockIdx.y;
    int t = blockIdx.x * 256 + threadIdx.x;
    const float* p = Y2 + (size_t)b * Hc * Tn + t;
    float m = g_mean[b * Tn + t];
    float r = g_rstd[b * Tn + t];
    float acc = 0.f;
#pragma unroll 8
    for (int h = 0; h < Hc; h++) {
        float v = (__ldg(p + (size_t)h * Tn) - m) * r * __ldg(g + h) + __ldg(be + h);
        acc += fmaxf(v, 0.f) * __ldg(Wl + h);
    }
    float z = fmaxf(acc + __ldg(bl), 0.f);
    int d = (int)floorf(expf(z));
    g_dur[b * Tn + t] = d;
    durF[b * Tn + t] = (float)d;
}

__global__ void cumsum_k()
{
    __shared__ int s[Tn];
    int b = blockIdx.x, t = threadIdx.x;
    s[t] = g_dur[b * Tn + t];
    __syncthreads();
#pragma unroll
    for (int off = 1; off < Tn; off <<= 1) {
        int v = (t >= off) ? s[t - off] : 0;
        __syncthreads();
        s[t] += v;
        __syncthreads();
    }
    g_cum[b * Tn + t] = s[t];
}

__global__ void gather_k(const float* __restrict__ X, float* __restrict__ outAligned)
{
    __shared__ int sc[Tn];
    int b = blockIdx.y;
    int tid = threadIdx.x;
#pragma unroll
    for (int e = 0; e < 4; e++) sc[tid + 256 * e] = g_cum[b * Tn + tid + 256 * e];
    __syncthreads();

    int pos = blockIdx.x * 256 + tid;
    int total = sc[Tn - 1];
    bool valid = pos < total;
    int lo = 0, hi = Tn;
    while (lo < hi) {
        int mid = (lo + hi) >> 1;
        if (sc[mid] <= pos) lo = mid + 1; else hi = mid;
    }
    int idx = min(lo, Tn - 1);

    const float* xb = X + (size_t)b * Hc * Tn;
    float* ob = outAligned + (size_t)b * Hc * MAXL + pos;
    if (valid) {
#pragma unroll 4
        for (int h = 0; h < Hc; h++) ob[(size_t)h * MAXL] = __ldg(xb + (size_t)h * Tn + idx);
    } else {
#pragma unroll 4
        for (int h = 0; h < Hc; h++) ob[(size_t)h * MAXL] = 0.f;
    }
}

// ---------------------------------------------------------------------------------
extern "C" void kernel_launch(void* const* d_in, const int* in_sizes, int n_in,
                              void* d_out, int out_size)
{
    const float* x  = (const float*)d_in[0];
    const float* W1 = (const float*)d_in[1];
    const float* b1 = (const float*)d_in[2];
    const float* g1 = (const float*)d_in[3];
    const float* be1= (const float*)d_in[4];
    const float* W2 = (const float*)d_in[5];
    const float* b2 = (const float*)d_in[6];
    const float* g2 = (const float*)d_in[7];
    const float* be2= (const float*)d_in[8];
    const float* Wl = (const float*)d_in[9];
    const float* bl = (const float*)d_in[10];

    float* out = (float*)d_out;
    float* outDur     = out;
    float* outAligned = out + Bq * Tn;

    float *buf1, *buf2, *Mbuf, *Vf, *Bf;
    cudaGetSymbolAddress((void**)&buf1, g_buf1);
    cudaGetSymbolAddress((void**)&buf2, g_buf2);
    cudaGetSymbolAddress((void**)&Mbuf, g_M);
    cudaGetSymbolAddress((void**)&Vf, g_Vf);
    cudaGetSymbolAddress((void**)&Bf, g_Bf);
    float* Bf1 = Bf;
    float* Bf2 = Bf + 4 * 2 * KT * NT * 64;

    dim3 mma_grid(NTOT / 128, Hc / 128, 4);   // (128, 3, 4)
    dim3 ln_grid(Tn / 256, Bq);

    bprep<<<(KT * NT) / 8, 256>>>(W1, Bf1);   // 288 blocks
    bprep<<<(KT * NT) / 8, 256>>>(W2, Bf2);

    // conv1
    vprep<<<(KT * MT) / 8, 256>>>(x, Vf);     // 6144 blocks
    wino_mma<<<mma_grid, 256>>>(Vf, Bf1, Mbuf);
    wino_out<<<(Bq * Hc * NBLK) / 256, 256>>>(Mbuf, b1, buf1);
    ln_stats<<<ln_grid, 256>>>(buf1);
    ln_apply_relu<<<(Bq * Hc * Tn) / 256, 256>>>(buf1, g1, be1);
    // conv2
    vprep<<<(KT * MT) / 8, 256>>>(buf1, Vf);
    wino_mma<<<mma_grid, 256>>>(Vf, Bf2, Mbuf);
    wino_out<<<(Bq * Hc * NBLK) / 256, 256>>>(Mbuf, b2, buf2);
    ln_stats<<<ln_grid, 256>>>(buf2);
    ln_dot_dur<<<ln_grid, 256>>>(buf2, g2, be2, Wl, bl, outDur);

    cumsum_k<<<Bq, Tn>>>();
    gather_k<<<dim3(MAXL / 256, Bq), 256>>>(x, outAligned);
}